// round 15
// baseline (speedup 1.0000x reference)
#include <cuda_runtime.h>
#include <math.h>

// B=4, C=3=heads, c_h=1, H=W=64, N=4096, scale=1
#define BATCH 4
#define CH 3
#define NPIX 4096
#define NBH 12
#define NBINS 16
#define HBINS (NBINS / 2)
#define LOG2E 1.4426950408889634f
#define LN2   0.6931471805599453f
#define GRID  128
#define BPB   32          // blocks per batch
#define NTHR  768
#define NWARP (NTHR / 32)

// Ping-pong moment accumulators: per bin ONE float4 {S0=sum v, S1=sum v*d, T0=count, T1=sum d}
__device__ float4 g_mom4[2][NBH][NBINS];
__device__ unsigned g_cnt[BATCH] = {0, 0, 0, 0};
__device__ unsigned g_gen[BATCH] = {0, 0, 0, 0};

__device__ __forceinline__ float ex2f(float x) {
    float y;
    asm("ex2.approx.f32 %0, %1;" : "=f"(y) : "f"(x));
    return y;
}

__device__ __forceinline__ void red_v4(float4* p, float a, float b, float c, float d) {
    asm volatile("red.global.add.v4.f32 [%0], {%1,%2,%3,%4};"
                 :: "l"(p), "f"(a), "f"(b), "f"(c), "f"(d) : "memory");
}
__device__ __forceinline__ unsigned atom_add_acqrel(unsigned* p, unsigned v) {
    unsigned old;
    asm volatile("atom.acq_rel.gpu.global.add.u32 %0, [%1], %2;"
                 : "=r"(old) : "l"(p), "r"(v) : "memory");
    return old;
}
__device__ __forceinline__ void red_add_release(unsigned* p, unsigned v) {
    asm volatile("red.release.gpu.global.add.u32 [%0], %1;"
                 :: "l"(p), "r"(v) : "memory");
}
__device__ __forceinline__ unsigned ld_acquire(const unsigned* p) {
    unsigned v;
    asm volatile("ld.acquire.gpu.global.u32 %0, [%1];" : "=r"(v) : "l"(p) : "memory");
    return v;
}

__device__ __forceinline__ float warp_sum(float v) {
    #pragma unroll
    for (int o = 16; o; o >>= 1) v += __shfl_down_sync(0xFFFFFFFFu, v, o);
    return v;
}

__device__ __forceinline__ float block_sum(float v, float* sh, float* bcast) {
    v = warp_sum(v);
    int lane = threadIdx.x & 31, w = threadIdx.x >> 5;
    if (lane == 0) sh[w] = v;
    __syncthreads();
    if (w == 0) {
        float r = (lane < NWARP) ? sh[lane] : 0.f;
        r = warp_sum(r);
        if (lane == 0) *bcast = r;
    }
    __syncthreads();
    return *bcast;
}

__device__ __forceinline__ float2 block_sum2(float a, float b, float2* sh, float2* bcast) {
    a = warp_sum(a);
    b = warp_sum(b);
    int lane = threadIdx.x & 31, w = threadIdx.x >> 5;
    if (lane == 0) sh[w] = make_float2(a, b);
    __syncthreads();
    if (w == 0) {
        float2 rv = (lane < NWARP) ? sh[lane] : make_float2(0.f, 0.f);
        rv.x = warp_sum(rv.x);
        rv.y = warp_sum(rv.y);
        if (lane == 0) *bcast = rv;
    }
    __syncthreads();
    return *bcast;
}

__global__ void __launch_bounds__(NTHR) fused_kernel(
    const float* __restrict__ rgb,
    const float* __restrict__ wq,
    const float* __restrict__ wk,
    const float* __restrict__ wv,
    const float* __restrict__ wo,
    float* __restrict__ out)
{
    __shared__ float  s_red[NWARP];
    __shared__ float2 s_red2[NWARP];
    __shared__ float  s_bc1;
    __shared__ float2 s_bc2;
    __shared__ float  s_wo[9];
    __shared__ float  s_bins[CH * NBINS * 4];  // 768 B block-local moment bins
    __shared__ float4 s_mom[CH * NBINS];       // 768 B
    __shared__ float2 s_nd[NTHR];              // 6 KB

    const int bx = blockIdx.x;
    const int b = bx >> 5;
    const int chunk = bx & 31;
    const int t = threadIdx.x;
    const int half = (t >= 384) ? 1 : 0;
    const int task = t - half * 384;           // 0..383
    const int ch = task >> 7;                  // warp-uniform
    const int p = task & 127;
    const int n = (chunk << 7) + p;

    const unsigned gen0 = ld_acquire(&g_gen[b]);
    const int pb = (int)(gen0 & 1u);
    const int ab = pb ^ 1;

    // ---- Prefetch: own pixel + weight rows (overlaps with luma loop) ----
    const float* base = rgb + (size_t)b * CH * NPIX;
    float rr = base[n];
    float gg = base[NPIX + n];
    float bb = base[2 * NPIX + n];
    float wq0 = wq[3 * ch], wq1 = wq[3 * ch + 1], wq2 = wq[3 * ch + 2];
    float w0  = wk[3 * ch], w1  = wk[3 * ch + 1], w2  = wk[3 * ch + 2];
    float wv0 = wv[3 * ch], wv1 = wv[3 * ch + 1], wv2 = wv[3 * ch + 2];
    if (t < 9) s_wo[t] = wo[t];

    // zero block-local bins + slice of alternate global buffer
    if (t < CH * NBINS * 4) s_bins[t] = 0.f;
    {   // alt buffer: 12*16 float4 = 768 floats / 128 blocks = 6 each
        float* alt = (float*)&g_mom4[ab][0][0];
        if (t >= 576 && t < 582) alt[bx * 6 + (t - 576)] = 0.f;
    }

    // ---- Phase A: vectorized batch luma, all in registers ----
    const float4* b4 = (const float4*)base;    // planes: r[0,1024) g[1024,2048) b[2048,3072)
    float4 La, Lb = make_float4(0.f, 0.f, 0.f, 0.f);
    float accL;
    {
        float4 r4 = b4[t], g4 = b4[1024 + t], v4 = b4[2048 + t];
        La.x = 0.299f * r4.x + 0.587f * g4.x + 0.114f * v4.x;
        La.y = 0.299f * r4.y + 0.587f * g4.y + 0.114f * v4.y;
        La.z = 0.299f * r4.z + 0.587f * g4.z + 0.114f * v4.z;
        La.w = 0.299f * r4.w + 0.587f * g4.w + 0.114f * v4.w;
        accL = (La.x + La.y) + (La.z + La.w);
    }
    if (t >= 512) {                            // extras on half=1 threads
        int i = t + 256;                       // 768..1023
        float4 r4 = b4[i], g4 = b4[1024 + i], v4 = b4[2048 + i];
        Lb.x = 0.299f * r4.x + 0.587f * g4.x + 0.114f * v4.x;
        Lb.y = 0.299f * r4.y + 0.587f * g4.y + 0.114f * v4.y;
        Lb.z = 0.299f * r4.z + 0.587f * g4.z + 0.114f * v4.z;
        Lb.w = 0.299f * r4.w + 0.587f * g4.w + 0.114f * v4.w;
        accL += (Lb.x + Lb.y) + (Lb.z + Lb.w);
    }
    float mu = block_sum(accL, s_red, &s_bc1) * (1.0f / NPIX);

    // ---- |L - mu| sums from registers ----
    float a1, a2;
    {
        float d0 = fabsf(La.x - mu), d1 = fabsf(La.y - mu);
        float d2 = fabsf(La.z - mu), d3 = fabsf(La.w - mu);
        a1 = (d0 + d1) + (d2 + d3);
        a2 = fmaf(d0, d0, fmaf(d1, d1, fmaf(d2, d2, d3 * d3)));
    }
    if (t >= 512) {
        float d0 = fabsf(Lb.x - mu), d1 = fabsf(Lb.y - mu);
        float d2 = fabsf(Lb.z - mu), d3 = fabsf(Lb.w - mu);
        a1 += (d0 + d1) + (d2 + d3);
        a2 += fmaf(d0, d0, fmaf(d1, d1, fmaf(d2, d2, d3 * d3)));
    }
    float2 S = block_sum2(a1, a2, s_red2, &s_bc2);
    float var = (S.y - S.x * S.x * (1.0f / NPIX)) * (1.0f / (NPIX - 1));
    float inv_std = 1.0f / (sqrtf(fmaxf(var, 0.f)) + 1e-6f);

    // ---- Gate + q ----
    float Ln = 0.299f * rr + 0.587f * gg + 0.114f * bb;
    float dL = fabsf(Ln - mu);
    float gate = 1.0f / (1.0f + ex2f(-dL * inv_std * LOG2E));
    float gf = 1.0f + gate;
    float q = (wq0 * rr + wq1 * gg + wq2 * bb) * gf;

    // bin geometry from wk row (exact bounds: rgb in [0,1])
    float mn = fminf(w0, 0.f) + fminf(w1, 0.f) + fminf(w2, 0.f);
    float mx = fmaxf(w0, 0.f) + fmaxf(w1, 0.f) + fmaxf(w2, 0.f);
    float kmin2 = mn * LOG2E;
    float delta = (mx - mn) * (LOG2E / NBINS);
    if (delta < 1e-20f) delta = 1e-20f;
    float cen0 = kmin2 + 0.5f * delta;

    // ---- SMEM pre-aggregation of 1st-order moments (half 0 only) ----
    if (half == 0) {
        float k = (w0 * rr + w1 * gg + w2 * bb);
        float v = (wv0 * rr + wv1 * gg + wv2 * bb);
        float k2 = k * LOG2E;
        int j = (int)((k2 - kmin2) * (1.0f / delta));
        j = max(0, min(NBINS - 1, j));
        float d2 = k2 - fmaf((float)j, delta, cen0);
        float* sb = &s_bins[(ch * NBINS + j) * 4];
        atomicAdd(sb + 0, v);
        atomicAdd(sb + 1, v * d2);
        atomicAdd(sb + 2, 1.0f);
        atomicAdd(sb + 3, d2);
    }
    __syncthreads();

    // ---- Flush block bins: ONE red.v4 per bin (32 REDs/address total) ----
    if (t < CH * NBINS) {
        const float* sb = &s_bins[t * 4];
        float4* mp = &g_mom4[pb][b * CH][0] + t;
        if (sb[2] != 0.f) {
            red_v4(mp, sb[0], sb[1], sb[2], sb[3]);
        }
    }

    // ---- per-batch grid barrier (32 blocks), acq/rel scoped, t0-spin ----
    __syncthreads();
    if (t == 0) {
        if (atom_add_acqrel(&g_cnt[b], 1) == BPB - 1) {
            asm volatile("st.relaxed.gpu.global.u32 [%0], %1;" :: "l"(&g_cnt[b]), "r"(0u) : "memory");
            red_add_release(&g_gen[b], 1);
        } else {
            while (ld_acquire(&g_gen[b]) == gen0) { }
        }
    }
    __syncthreads();

    // ---- Stage moments (48 ldcg float4) ----
    {
        const float4* gm4 = &g_mom4[pb][b * CH][0];
        if (t < CH * NBINS) s_mom[t] = __ldcg(&gm4[t]);
    }
    __syncthreads();

    // ---- Eval (split halves over bins; 8 bins each; 1st-order) ----
    float u = q * LN2;
    float step = q * delta;
    float c0 = q * cen0;
    float cL = fmaf((float)(NBINS - 1), step, c0);
    float offs = -fmaxf(c0, cL);                // global row max
    float arg = fmaf((float)(half * HBINS), step, c0) + offs;
    float step2 = step + step;

    float n0 = 0.f, n1 = 0.f, d0a = 0.f, d1a = 0.f;
    const float4* sp = s_mom + ch * NBINS + half * HBINS;

    #pragma unroll
    for (int jj = 0; jj < HBINS; jj += 2) {
        float4 A0 = sp[jj];
        float4 A1 = sp[jj + 1];
        float e0 = ex2f(arg);
        float e1 = ex2f(arg + step);
        arg += step2;
        float pn0 = fmaf(u, A0.y, A0.x);
        float pd0 = fmaf(u, A0.w, A0.z);
        n0 = fmaf(e0, pn0, n0);
        d0a = fmaf(e0, pd0, d0a);
        float pn1 = fmaf(u, A1.y, A1.x);
        float pd1 = fmaf(u, A1.w, A1.z);
        n1 = fmaf(e1, pn1, n1);
        d1a = fmaf(e1, pd1, d1a);
    }
    s_nd[t] = make_float2(n0 + n1, d0a + d1a);
    __syncthreads();

    // ---- Combine halves + channels directly, residual, clip, store ----
    if (t < 128) {
        float2 l0 = s_nd[t],       h0 = s_nd[t + 384];
        float2 l1 = s_nd[128 + t], h1 = s_nd[512 + t];
        float2 l2 = s_nd[256 + t], h2v = s_nd[640 + t];
        float a0  = __fdividef(l0.x + h0.x, l0.y + h0.y);
        float a1o = __fdividef(l1.x + h1.x, l1.y + h1.y);
        float a2o = __fdividef(l2.x + h2v.x, l2.y + h2v.y);
        float pr[3] = {rr, gg, bb};
        #pragma unroll
        for (int c = 0; c < 3; c++) {
            float o = s_wo[3 * c] * a0 + s_wo[3 * c + 1] * a1o + s_wo[3 * c + 2] * a2o;
            size_t off = ((size_t)b * CH + c) * NPIX + n;
            float val = pr[c] + o;
            out[off] = fminf(fmaxf(val, 0.f), 1.f);
        }
    }
}

extern "C" void kernel_launch(void* const* d_in, const int* in_sizes, int n_in,
                              void* d_out, int out_size)
{
    const float* rgb = (const float*)d_in[0];
    const float* wq  = (const float*)d_in[1];
    const float* wk  = (const float*)d_in[2];
    const float* wv  = (const float*)d_in[3];
    const float* wo  = (const float*)d_in[4];
    float* out = (float*)d_out;

    fused_kernel<<<GRID, NTHR>>>(rgb, wq, wk, wv, wo, out);
}

// round 16
// speedup vs baseline: 1.0342x; 1.0342x over previous
#include <cuda_runtime.h>
#include <math.h>

// B=4, C=3=heads, c_h=1, H=W=64, N=4096, scale=1
#define BATCH 4
#define CH 3
#define NPIX 4096
#define NBH 12
#define NBINS 32
#define HBINS (NBINS / 2)
#define LOG2E 1.4426950408889634f
#define LN2   0.6931471805599453f
#define GRID  128
#define BPB   32          // blocks per batch
#define NTHR  768
#define NWARP (NTHR / 32)

// Ping-pong moment accumulators: per bin ONE float4 {S0=sum v, S1=sum v*d, T0=count, T1=sum d}
__device__ float4 g_mom4[2][NBH][NBINS];
// Monotonic arrival counter per batch: +BPB per launch; parity = (gen>>5)&1
__device__ unsigned g_gen[BATCH] = {0, 0, 0, 0};

__device__ __forceinline__ float ex2f(float x) {
    float y;
    asm("ex2.approx.f32 %0, %1;" : "=f"(y) : "f"(x));
    return y;
}

__device__ __forceinline__ void red_v4(float4* p, float a, float b, float c, float d) {
    asm volatile("red.global.add.v4.f32 [%0], {%1,%2,%3,%4};"
                 :: "l"(p), "f"(a), "f"(b), "f"(c), "f"(d) : "memory");
}
__device__ __forceinline__ void red_add_release(unsigned* p, unsigned v) {
    asm volatile("red.release.gpu.global.add.u32 [%0], %1;"
                 :: "l"(p), "r"(v) : "memory");
}
__device__ __forceinline__ unsigned ld_acquire(const unsigned* p) {
    unsigned v;
    asm volatile("ld.acquire.gpu.global.u32 %0, [%1];" : "=r"(v) : "l"(p) : "memory");
    return v;
}

__device__ __forceinline__ float warp_sum(float v) {
    #pragma unroll
    for (int o = 16; o; o >>= 1) v += __shfl_down_sync(0xFFFFFFFFu, v, o);
    return v;
}

__device__ __forceinline__ float block_sum(float v, float* sh, float* bcast) {
    v = warp_sum(v);
    int lane = threadIdx.x & 31, w = threadIdx.x >> 5;
    if (lane == 0) sh[w] = v;
    __syncthreads();
    if (w == 0) {
        float r = (lane < NWARP) ? sh[lane] : 0.f;
        r = warp_sum(r);
        if (lane == 0) *bcast = r;
    }
    __syncthreads();
    return *bcast;
}

__device__ __forceinline__ float2 block_sum2(float a, float b, float2* sh, float2* bcast) {
    a = warp_sum(a);
    b = warp_sum(b);
    int lane = threadIdx.x & 31, w = threadIdx.x >> 5;
    if (lane == 0) sh[w] = make_float2(a, b);
    __syncthreads();
    if (w == 0) {
        float2 rv = (lane < NWARP) ? sh[lane] : make_float2(0.f, 0.f);
        rv.x = warp_sum(rv.x);
        rv.y = warp_sum(rv.y);
        if (lane == 0) *bcast = rv;
    }
    __syncthreads();
    return *bcast;
}

__global__ void __launch_bounds__(NTHR) fused_kernel(
    const float* __restrict__ rgb,
    const float* __restrict__ wq,
    const float* __restrict__ wk,
    const float* __restrict__ wv,
    const float* __restrict__ wo,
    float* __restrict__ out)
{
    __shared__ float  s_red[NWARP];
    __shared__ float2 s_red2[NWARP];
    __shared__ float  s_bc1;
    __shared__ float2 s_bc2;
    __shared__ float  s_bins[CH * NBINS * 4];  // 1.5 KB block-local moment bins
    __shared__ float4 s_mom[CH * NBINS];       // 1.5 KB
    __shared__ float2 s_nd[NTHR];              // 6 KB

    const int bx = blockIdx.x;
    const int b = bx >> 5;
    const int chunk = bx & 31;
    const int t = threadIdx.x;
    const int half = (t >= 384) ? 1 : 0;
    const int task = t - half * 384;           // 0..383
    const int ch = task >> 7;                  // warp-uniform
    const int p = task & 127;
    const int n = (chunk << 7) + p;

    const unsigned gen0 = ld_acquire(&g_gen[b]);   // = BPB * launch_index (stream-serialized replays)
    const int pb = (int)((gen0 >> 5) & 1u);
    const int ab = pb ^ 1;

    // ---- Prefetch: own pixel + weight rows (overlaps with luma loop) ----
    const float* base = rgb + (size_t)b * CH * NPIX;
    float rr = base[n];
    float gg = base[NPIX + n];
    float bb = base[2 * NPIX + n];
    float wq0 = wq[3 * ch], wq1 = wq[3 * ch + 1], wq2 = wq[3 * ch + 2];
    float w0  = wk[3 * ch], w1  = wk[3 * ch + 1], w2  = wk[3 * ch + 2];
    float wv0 = wv[3 * ch], wv1 = wv[3 * ch + 1], wv2 = wv[3 * ch + 2];

    // zero block-local bins + slice of alternate global buffer
    if (t < CH * NBINS * 4) s_bins[t] = 0.f;
    {   // alt buffer: 12*32 float4 = 1536 floats / 128 blocks = 12 each
        float* alt = (float*)&g_mom4[ab][0][0];
        if (t >= 576 && t < 588) alt[bx * 12 + (t - 576)] = 0.f;
    }

    // ---- Phase A: vectorized batch luma, all in registers ----
    const float4* b4 = (const float4*)base;    // planes: r[0,1024) g[1024,2048) b[2048,3072)
    float4 La, Lb = make_float4(0.f, 0.f, 0.f, 0.f);
    float accL;
    {
        float4 r4 = b4[t], g4 = b4[1024 + t], v4 = b4[2048 + t];
        La.x = 0.299f * r4.x + 0.587f * g4.x + 0.114f * v4.x;
        La.y = 0.299f * r4.y + 0.587f * g4.y + 0.114f * v4.y;
        La.z = 0.299f * r4.z + 0.587f * g4.z + 0.114f * v4.z;
        La.w = 0.299f * r4.w + 0.587f * g4.w + 0.114f * v4.w;
        accL = (La.x + La.y) + (La.z + La.w);
    }
    if (t >= 512) {                            // extras on half=1 threads
        int i = t + 256;                       // 768..1023
        float4 r4 = b4[i], g4 = b4[1024 + i], v4 = b4[2048 + i];
        Lb.x = 0.299f * r4.x + 0.587f * g4.x + 0.114f * v4.x;
        Lb.y = 0.299f * r4.y + 0.587f * g4.y + 0.114f * v4.y;
        Lb.z = 0.299f * r4.z + 0.587f * g4.z + 0.114f * v4.z;
        Lb.w = 0.299f * r4.w + 0.587f * g4.w + 0.114f * v4.w;
        accL += (Lb.x + Lb.y) + (Lb.z + Lb.w);
    }
    float mu = block_sum(accL, s_red, &s_bc1) * (1.0f / NPIX);

    // ---- |L - mu| sums from registers ----
    float a1, a2;
    {
        float d0 = fabsf(La.x - mu), d1 = fabsf(La.y - mu);
        float d2 = fabsf(La.z - mu), d3 = fabsf(La.w - mu);
        a1 = (d0 + d1) + (d2 + d3);
        a2 = fmaf(d0, d0, fmaf(d1, d1, fmaf(d2, d2, d3 * d3)));
    }
    if (t >= 512) {
        float d0 = fabsf(Lb.x - mu), d1 = fabsf(Lb.y - mu);
        float d2 = fabsf(Lb.z - mu), d3 = fabsf(Lb.w - mu);
        a1 += (d0 + d1) + (d2 + d3);
        a2 += fmaf(d0, d0, fmaf(d1, d1, fmaf(d2, d2, d3 * d3)));
    }
    float2 S = block_sum2(a1, a2, s_red2, &s_bc2);
    float var = (S.y - S.x * S.x * (1.0f / NPIX)) * (1.0f / (NPIX - 1));
    float inv_std = 1.0f / (sqrtf(fmaxf(var, 0.f)) + 1e-6f);

    // ---- Gate + q ----
    float Ln = 0.299f * rr + 0.587f * gg + 0.114f * bb;
    float dL = fabsf(Ln - mu);
    float gate = 1.0f / (1.0f + ex2f(-dL * inv_std * LOG2E));
    float gf = 1.0f + gate;
    float q = (wq0 * rr + wq1 * gg + wq2 * bb) * gf;

    // bin geometry from wk row (exact bounds: rgb in [0,1])
    float mn = fminf(w0, 0.f) + fminf(w1, 0.f) + fminf(w2, 0.f);
    float mx = fmaxf(w0, 0.f) + fmaxf(w1, 0.f) + fmaxf(w2, 0.f);
    float kmin2 = mn * LOG2E;
    float delta = (mx - mn) * (LOG2E / NBINS);
    if (delta < 1e-20f) delta = 1e-20f;
    float cen0 = kmin2 + 0.5f * delta;

    // ---- SMEM pre-aggregation of 1st-order moments (half 0 only) ----
    if (half == 0) {
        float k = (w0 * rr + w1 * gg + w2 * bb);
        float v = (wv0 * rr + wv1 * gg + wv2 * bb);
        float k2 = k * LOG2E;
        int j = (int)((k2 - kmin2) * (1.0f / delta));
        j = max(0, min(NBINS - 1, j));
        float d2 = k2 - fmaf((float)j, delta, cen0);
        float* sb = &s_bins[(ch * NBINS + j) * 4];
        atomicAdd(sb + 0, v);
        atomicAdd(sb + 1, v * d2);
        atomicAdd(sb + 2, 1.0f);
        atomicAdd(sb + 3, d2);
    }
    __syncthreads();

    // ---- Flush block bins: ONE red.v4 per bin (32 REDs/address total) ----
    if (t < CH * NBINS) {
        const float* sb = &s_bins[t * 4];
        float4* mp = &g_mom4[pb][b * CH][0] + t;
        if (sb[2] != 0.f) {
            red_v4(mp, sb[0], sb[1], sb[2], sb[3]);
        }
    }

    // ---- per-batch barrier: fire-and-forget RED arrival, spin to target ----
    __syncthreads();
    if (t == 0) {
        red_add_release(&g_gen[b], 1);         // no-return: SM does not wait
        const unsigned target = gen0 + BPB;    // 32nd RED IS the release
        while ((int)(ld_acquire(&g_gen[b]) - target) < 0) { }
    }
    __syncthreads();

    // ---- Stage moments (96 ldcg float4) ----
    {
        const float4* gm4 = &g_mom4[pb][b * CH][0];
        if (t < CH * NBINS) s_mom[t] = __ldcg(&gm4[t]);
    }
    __syncthreads();

    // ---- Eval (split halves over bins; 16 bins each; 1st-order) ----
    float u = q * LN2;
    float step = q * delta;
    float c0 = q * cen0;
    float cL = fmaf((float)(NBINS - 1), step, c0);
    float offs = -fmaxf(c0, cL);                // global row max
    float arg = fmaf((float)(half * HBINS), step, c0) + offs;
    float step2 = step + step;

    float n0 = 0.f, n1 = 0.f, d0a = 0.f, d1a = 0.f;
    const float4* sp = s_mom + ch * NBINS + half * HBINS;

    #pragma unroll
    for (int jj = 0; jj < HBINS; jj += 2) {
        float4 A0 = sp[jj];
        float4 A1 = sp[jj + 1];
        float e0 = ex2f(arg);
        float e1 = ex2f(arg + step);
        arg += step2;
        float pn0 = fmaf(u, A0.y, A0.x);
        float pd0 = fmaf(u, A0.w, A0.z);
        n0 = fmaf(e0, pn0, n0);
        d0a = fmaf(e0, pd0, d0a);
        float pn1 = fmaf(u, A1.y, A1.x);
        float pd1 = fmaf(u, A1.w, A1.z);
        n1 = fmaf(e1, pn1, n1);
        d1a = fmaf(e1, pd1, d1a);
    }
    s_nd[t] = make_float2(n0 + n1, d0a + d1a);
    __syncthreads();

    // ---- Combine halves + channels directly, residual, clip, store ----
    if (t < 128) {
        float2 l0 = s_nd[t],       h0 = s_nd[t + 384];
        float2 l1 = s_nd[128 + t], h1 = s_nd[512 + t];
        float2 l2 = s_nd[256 + t], h2v = s_nd[640 + t];
        float a0  = __fdividef(l0.x + h0.x, l0.y + h0.y);
        float a1o = __fdividef(l1.x + h1.x, l1.y + h1.y);
        float a2o = __fdividef(l2.x + h2v.x, l2.y + h2v.y);
        float pr[3] = {rr, gg, bb};
        #pragma unroll
        for (int c = 0; c < 3; c++) {
            float o = wo[3 * c] * a0 + wo[3 * c + 1] * a1o + wo[3 * c + 2] * a2o;
            size_t off = ((size_t)b * CH + c) * NPIX + n;
            float val = pr[c] + o;
            out[off] = fminf(fmaxf(val, 0.f), 1.f);
        }
    }
}

extern "C" void kernel_launch(void* const* d_in, const int* in_sizes, int n_in,
                              void* d_out, int out_size)
{
    const float* rgb = (const float*)d_in[0];
    const float* wq  = (const float*)d_in[1];
    const float* wk  = (const float*)d_in[2];
    const float* wv  = (const float*)d_in[3];
    const float* wo  = (const float*)d_in[4];
    float* out = (float*)d_out;

    fused_kernel<<<GRID, NTHR>>>(rgb, wq, wk, wv, wo, out);
}